// round 15
// baseline (speedup 1.0000x reference)
#include <cuda_runtime.h>
#include <cuda_fp16.h>
#include <cstdint>

#define BATCH 256
#define N_GENES 8192
#define WM 4
#define HID (N_GENES * WM)       // 32768
#define N_TF 1024
#define GPT 64
#define EDGES3 (GPT * WM)        // 256
#define EPS 1e-5f
#define GENES_PER_BLOCK 8
#define N_TILES (N_GENES / GENES_PER_BLOCK)   // 1024
#define GRID 444                 // 148 SMs x 3 resident blocks (GB300 has 152)

// Scratch: layer-2 output stored TRANSPOSED in fp16: hT[col * BATCH + b]
__device__ __half g_hT[HID * BATCH];
// Monotonic grid-barrier counter (zero-initialized at module load; never reset
// -> safe across the correctness run + every graph replay).
__device__ unsigned g_bar;

typedef unsigned long long u64;

// ---- packed fp32x2 ops (Blackwell sm_103a) ----
__device__ __forceinline__ u64 pk2(float lo, float hi) {
    u64 r; asm("mov.b64 %0, {%1, %2};" : "=l"(r) : "f"(lo), "f"(hi)); return r;
}
__device__ __forceinline__ void upk2(u64 v, float& lo, float& hi) {
    asm("mov.b64 {%0, %1}, %2;" : "=f"(lo), "=f"(hi) : "l"(v));
}
__device__ __forceinline__ u64 fma2(u64 a, u64 b, u64 c) {
    u64 d; asm("fma.rn.f32x2 %0, %1, %2, %3;" : "=l"(d) : "l"(a), "l"(b), "l"(c)); return d;
}
__device__ __forceinline__ u64 add2(u64 a, u64 b) {
    u64 d; asm("add.rn.f32x2 %0, %1, %2;" : "=l"(d) : "l"(a), "l"(b)); return d;
}
__device__ __forceinline__ u64 mul2(u64 a, u64 b) {
    u64 d; asm("mul.rn.f32x2 %0, %1, %2;" : "=l"(d) : "l"(a), "l"(b)); return d;
}
__device__ __forceinline__ u64 relu2(u64 a) {
    float x, y; upk2(a, x, y);
    return pk2(fmaxf(x, 0.f), fmaxf(y, 0.f));
}

__device__ __forceinline__ float2 warp_sum2(float2 v) {
#pragma unroll
    for (int o = 16; o; o >>= 1) {
        v.x += __shfl_xor_sync(0xffffffffu, v.x, o);
        v.y += __shfl_xor_sync(0xffffffffu, v.y, o);
    }
    return v;
}

struct __align__(8) H22 { __half2 a, b; };
struct __align__(8) WC { float w; int boff; };

__device__ __forceinline__ void fma8(float* acc, float w, const uint4& v) {
    float2 f0 = __half22float2(*reinterpret_cast<const __half2*>(&v.x));
    float2 f1 = __half22float2(*reinterpret_cast<const __half2*>(&v.y));
    float2 f2 = __half22float2(*reinterpret_cast<const __half2*>(&v.z));
    float2 f3 = __half22float2(*reinterpret_cast<const __half2*>(&v.w));
    acc[0] = fmaf(w, f0.x, acc[0]);
    acc[1] = fmaf(w, f0.y, acc[1]);
    acc[2] = fmaf(w, f1.x, acc[2]);
    acc[3] = fmaf(w, f1.y, acc[3]);
    acc[4] = fmaf(w, f2.x, acc[4]);
    acc[5] = fmaf(w, f2.y, acc[5]);
    acc[6] = fmaf(w, f3.x, acc[6]);
    acc[7] = fmaf(w, f3.y, acc[7]);
}

// Persistent fused kernel: phase 1 = layers 1+2 (R14 body), grid barrier,
// phase 2 = layer3 gather + BN (R14 body).
__global__ __launch_bounds__(256, 3) void k_fused(
    const float* __restrict__ x,
    const float* __restrict__ w1, const float* __restrict__ b1,
    const float* __restrict__ w2, const float* __restrict__ b2,
    const float* __restrict__ w3, const float* __restrict__ b3,
    const int* __restrict__ cols3,
    float* __restrict__ out)
{
    __shared__ float sxT[GENES_PER_BLOCK][260];
    __shared__ WC swc[EDGES3];
    __shared__ float sacc[8][BATCH];
    __shared__ float2 sred[8];

    const int t = threadIdx.x;
    const int warp = t >> 5;
    const int lane = t & 31;

    // ======================= Phase 1: layers 1+2 =======================
    for (int tile = blockIdx.x; tile < N_TILES; tile += GRID) {
        const int g0 = tile * GENES_PER_BLOCK;
        __syncthreads();   // protect sxT from previous iteration's readers

        // Coalesced tile load: lane pairs share a batch row.
        {
            const int part = t & 1;
#pragma unroll
            for (int it = 0; it < 2; it++) {
                const int r = (t >> 1) + 128 * it;
                float4 v = *reinterpret_cast<const float4*>(
                    x + (size_t)r * N_GENES + g0 + 4 * part);
                sxT[4 * part + 0][r] = v.x;
                sxT[4 * part + 1][r] = v.y;
                sxT[4 * part + 2][r] = v.z;
                sxT[4 * part + 3][r] = v.w;
            }
        }
        __syncthreads();

        const int g = g0 + warp;

        u64 xp[2][2];
#pragma unroll
        for (int k = 0; k < 2; k++) {
            float4 xv = *reinterpret_cast<const float4*>(&sxT[warp][128 * k + 4 * lane]);
            xp[k][0] = pk2(xv.x, xv.y);
            xp[k][1] = pk2(xv.z, xv.w);
        }

        float4 w1q = *reinterpret_cast<const float4*>(w1 + 4 * g);
        float4 b1q = *reinterpret_cast<const float4*>(b1 + 4 * g);
        float4 b2q = *reinterpret_cast<const float4*>(b2 + 4 * g);
        float w1v[4] = {w1q.x, w1q.y, w1q.z, w1q.w};
        float b1v[4] = {b1q.x, b1q.y, b1q.z, b1q.w};
        float b2v[4] = {b2q.x, b2q.y, b2q.z, b2q.w};

        u64 h1[2][2][4];
#pragma unroll
        for (int k = 0; k < 2; k++)
#pragma unroll
            for (int pp = 0; pp < 2; pp++)
#pragma unroll
                for (int j = 0; j < 4; j++) {
                    u64 w1p = pk2(w1v[j], w1v[j]);
                    u64 b1p = pk2(b1v[j], b1v[j]);
                    h1[k][pp][j] = relu2(fma2(w1p, xp[k][pp], b1p));
                }

        float m1[4], inv1[4];
#pragma unroll
        for (int j = 0; j < 4; j++) {
            u64 s = add2(add2(h1[0][0][j], h1[0][1][j]), add2(h1[1][0][j], h1[1][1][j]));
            u64 q = mul2(h1[0][0][j], h1[0][0][j]);
            q = fma2(h1[0][1][j], h1[0][1][j], q);
            q = fma2(h1[1][0][j], h1[1][0][j], q);
            q = fma2(h1[1][1][j], h1[1][1][j], q);
            float sx, sy, qx, qy;
            upk2(s, sx, sy); upk2(q, qx, qy);
            float2 ss = warp_sum2(make_float2(sx + sy, qx + qy));
            float m = ss.x * (1.0f / BATCH);
            float var = fmaxf(ss.y * (1.0f / BATCH) - m * m, 0.0f);
            m1[j] = m;
            inv1[j] = rsqrtf(var + EPS);
        }

        float w2f[16], b2f[4];
        {
            float4 w2q0 = *reinterpret_cast<const float4*>(w2 + 16 * g);
            float4 w2q1 = *reinterpret_cast<const float4*>(w2 + 16 * g + 4);
            float4 w2q2 = *reinterpret_cast<const float4*>(w2 + 16 * g + 8);
            float4 w2q3 = *reinterpret_cast<const float4*>(w2 + 16 * g + 12);
            float w2v[16] = {w2q0.x, w2q0.y, w2q0.z, w2q0.w,
                             w2q1.x, w2q1.y, w2q1.z, w2q1.w,
                             w2q2.x, w2q2.y, w2q2.z, w2q2.w,
                             w2q3.x, w2q3.y, w2q3.z, w2q3.w};
#pragma unroll
            for (int i = 0; i < 4; i++) {
                float bb = b2v[i];
#pragma unroll
                for (int j = 0; j < 4; j++) {
                    float wf = w2v[4 * i + j] * inv1[j];
                    w2f[4 * i + j] = wf;
                    bb -= wf * m1[j];
                }
                b2f[i] = bb;
            }
        }

        u64 h2[2][2][4];
#pragma unroll
        for (int k = 0; k < 2; k++)
#pragma unroll
            for (int pp = 0; pp < 2; pp++)
#pragma unroll
                for (int i = 0; i < 4; i++) {
                    u64 acc = pk2(b2f[i], b2f[i]);
#pragma unroll
                    for (int j = 0; j < 4; j++) {
                        u64 wp = pk2(w2f[4 * i + j], w2f[4 * i + j]);
                        acc = fma2(wp, h1[k][pp][j], acc);
                    }
                    h2[k][pp][i] = relu2(acc);
                }

#pragma unroll
        for (int i = 0; i < 4; i++) {
            u64 s = add2(add2(h2[0][0][i], h2[0][1][i]), add2(h2[1][0][i], h2[1][1][i]));
            u64 q = mul2(h2[0][0][i], h2[0][0][i]);
            q = fma2(h2[0][1][i], h2[0][1][i], q);
            q = fma2(h2[1][0][i], h2[1][0][i], q);
            q = fma2(h2[1][1][i], h2[1][1][i], q);
            float sx, sy, qx, qy;
            upk2(s, sx, sy); upk2(q, qx, qy);
            float2 ss = warp_sum2(make_float2(sx + sy, qx + qy));
            float m = ss.x * (1.0f / BATCH);
            float var = fmaxf(ss.y * (1.0f / BATCH) - m * m, 0.0f);
            float inv = rsqrtf(var + EPS);

            u64 inv2 = pk2(inv, inv);
            u64 sh2  = pk2(-m * inv, -m * inv);
            __half2* dst = reinterpret_cast<__half2*>(&g_hT[(4 * g + i) * BATCH]);
#pragma unroll
            for (int k = 0; k < 2; k++) {
                u64 p0 = fma2(h2[k][0][i], inv2, sh2);
                u64 p1 = fma2(h2[k][1][i], inv2, sh2);
                float a0, a1, a2, a3;
                upk2(p0, a0, a1); upk2(p1, a2, a3);
                H22 hv;
                hv.a = __floats2half2_rn(a0, a1);
                hv.b = __floats2half2_rn(a2, a3);
                *reinterpret_cast<H22*>(&dst[64 * k + 2 * lane]) = hv;
            }
        }
    }

    // ===================== Grid barrier (replay-safe) =====================
    __syncthreads();
    if (t == 0) {
        __threadfence();                               // release g_hT writes
        unsigned arr = atomicAdd(&g_bar, 1u);
        unsigned target = (arr / GRID + 1u) * GRID;    // all GRID blocks of this call
        for (;;) {
            unsigned cur;
            asm volatile("ld.acquire.gpu.u32 %0, [%1];" : "=r"(cur) : "l"(&g_bar) : "memory");
            if ((cur - target) < 0x80000000u) break;   // cur >= target (mod 2^32)
            __nanosleep(64);
        }
    }
    __syncthreads();

    // ======================= Phase 2: layer 3 =======================
    const char* hbase = reinterpret_cast<const char*>(g_hT) + lane * 16;

    for (int tf = blockIdx.x; tf < N_TF; tf += GRID) {
        __syncthreads();   // protect swc/sacc from previous iteration's readers

        swc[t].w    = w3[tf * EDGES3 + t];
        swc[t].boff = cols3[tf * EDGES3 + t] * (BATCH * 2);   // bytes
        __syncthreads();

        const int ebase = warp * 32;
        float acc[8];
#pragma unroll
        for (int s = 0; s < 8; s++) acc[s] = 0.f;

#pragma unroll
        for (int c = 0; c < 8; c++) {
            WC a0 = swc[ebase + 4 * c + 0];
            WC a1 = swc[ebase + 4 * c + 1];
            WC a2 = swc[ebase + 4 * c + 2];
            WC a3 = swc[ebase + 4 * c + 3];
            uint4 v0 = *reinterpret_cast<const uint4*>(hbase + a0.boff);
            uint4 v1 = *reinterpret_cast<const uint4*>(hbase + a1.boff);
            uint4 v2 = *reinterpret_cast<const uint4*>(hbase + a2.boff);
            uint4 v3 = *reinterpret_cast<const uint4*>(hbase + a3.boff);
            fma8(acc, a0.w, v0);
            fma8(acc, a1.w, v1);
            fma8(acc, a2.w, v2);
            fma8(acc, a3.w, v3);
        }

        *reinterpret_cast<float4*>(&sacc[warp][8 * lane])     = make_float4(acc[0], acc[1], acc[2], acc[3]);
        *reinterpret_cast<float4*>(&sacc[warp][8 * lane + 4]) = make_float4(acc[4], acc[5], acc[6], acc[7]);
        __syncthreads();

        float z = b3[tf];
#pragma unroll
        for (int w = 0; w < 8; w++) z += sacc[w][t];

        float2 ss = warp_sum2(make_float2(z, z * z));
        if (lane == 0) sred[warp] = ss;
        __syncthreads();
        float S = 0.f, S2 = 0.f;
#pragma unroll
        for (int i = 0; i < 8; i++) { S += sred[i].x; S2 += sred[i].y; }
        float m = S * (1.0f / BATCH);
        float var = fmaxf(S2 * (1.0f / BATCH) - m * m, 0.0f);
        float inv = rsqrtf(var + EPS);

        out[t * N_TF + tf] = (z - m) * inv;
    }
}

extern "C" void kernel_launch(void* const* d_in, const int* in_sizes, int n_in,
                              void* d_out, int out_size)
{
    const float* x  = (const float*)d_in[0];
    const float* w1 = (const float*)d_in[1];
    const float* b1 = (const float*)d_in[2];
    const float* w2 = (const float*)d_in[3];
    const float* b2 = (const float*)d_in[4];
    const float* w3 = (const float*)d_in[5];
    const float* b3 = (const float*)d_in[6];
    const int* cols3 = (const int*)d_in[12];
    float* out = (float*)d_out;

    k_fused<<<GRID, 256>>>(x, w1, b1, w2, b2, w3, b3, cols3, out);
}

// round 16
// speedup vs baseline: 1.1710x; 1.1710x over previous
#include <cuda_runtime.h>
#include <cuda_fp16.h>
#include <cstdint>

#define BATCH 256
#define N_GENES 8192
#define WM 4
#define HID (N_GENES * WM)       // 32768
#define N_TF 1024
#define GPT 64
#define EDGES3 (GPT * WM)        // 256
#define EPS 1e-5f
#define GENES_PER_BLOCK 8

// Scratch: layer-2 output stored TRANSPOSED in fp16: hT[col * BATCH + b]
__device__ __half g_hT[HID * BATCH];

typedef unsigned long long u64;

// ---- packed fp32x2 ops (Blackwell sm_103a) ----
__device__ __forceinline__ u64 pk2(float lo, float hi) {
    u64 r; asm("mov.b64 %0, {%1, %2};" : "=l"(r) : "f"(lo), "f"(hi)); return r;
}
__device__ __forceinline__ void upk2(u64 v, float& lo, float& hi) {
    asm("mov.b64 {%0, %1}, %2;" : "=f"(lo), "=f"(hi) : "l"(v));
}
__device__ __forceinline__ u64 fma2(u64 a, u64 b, u64 c) {
    u64 d; asm("fma.rn.f32x2 %0, %1, %2, %3;" : "=l"(d) : "l"(a), "l"(b), "l"(c)); return d;
}
__device__ __forceinline__ u64 add2(u64 a, u64 b) {
    u64 d; asm("add.rn.f32x2 %0, %1, %2;" : "=l"(d) : "l"(a), "l"(b)); return d;
}
__device__ __forceinline__ u64 mul2(u64 a, u64 b) {
    u64 d; asm("mul.rn.f32x2 %0, %1, %2;" : "=l"(d) : "l"(a), "l"(b)); return d;
}
__device__ __forceinline__ u64 relu2(u64 a) {
    float x, y; upk2(a, x, y);
    return pk2(fmaxf(x, 0.f), fmaxf(y, 0.f));
}

__device__ __forceinline__ float2 warp_sum2(float2 v) {
#pragma unroll
    for (int o = 16; o; o >>= 1) {
        v.x += __shfl_xor_sync(0xffffffffu, v.x, o);
        v.y += __shfl_xor_sync(0xffffffffu, v.y, o);
    }
    return v;
}

struct __align__(8) H22 { __half2 a, b; };

// Fused: layer1 -> relu -> BN -> layer2 -> relu -> BN. One warp per gene.
// (R14 body, unchanged; + PDL trigger at the end.)
__global__ __launch_bounds__(256, 3) void k_layers12(
    const float* __restrict__ x,    // [BATCH, N_GENES] row-major
    const float* __restrict__ w1, const float* __restrict__ b1,
    const float* __restrict__ w2, const float* __restrict__ b2)
{
    __shared__ float sxT[GENES_PER_BLOCK][260];

    const int g0 = blockIdx.x * GENES_PER_BLOCK;
    const int t = threadIdx.x;
    const int warp = t >> 5;
    const int lane = t & 31;

    // Coalesced tile load: lane pairs share a batch row.
    {
        const int part = t & 1;
#pragma unroll
        for (int it = 0; it < 2; it++) {
            const int r = (t >> 1) + 128 * it;
            float4 v = *reinterpret_cast<const float4*>(
                x + (size_t)r * N_GENES + g0 + 4 * part);
            sxT[4 * part + 0][r] = v.x;
            sxT[4 * part + 1][r] = v.y;
            sxT[4 * part + 2][r] = v.z;
            sxT[4 * part + 3][r] = v.w;
        }
    }
    __syncthreads();

    const int gi = warp;
    const int g = g0 + gi;

    u64 xp[2][2];
#pragma unroll
    for (int k = 0; k < 2; k++) {
        float4 xv = *reinterpret_cast<const float4*>(&sxT[gi][128 * k + 4 * lane]);
        xp[k][0] = pk2(xv.x, xv.y);
        xp[k][1] = pk2(xv.z, xv.w);
    }

    float4 w1q = *reinterpret_cast<const float4*>(w1 + 4 * g);
    float4 b1q = *reinterpret_cast<const float4*>(b1 + 4 * g);
    float4 b2q = *reinterpret_cast<const float4*>(b2 + 4 * g);
    float w1v[4] = {w1q.x, w1q.y, w1q.z, w1q.w};
    float b1v[4] = {b1q.x, b1q.y, b1q.z, b1q.w};
    float b2v[4] = {b2q.x, b2q.y, b2q.z, b2q.w};

    u64 h1[2][2][4];
#pragma unroll
    for (int k = 0; k < 2; k++)
#pragma unroll
        for (int pp = 0; pp < 2; pp++)
#pragma unroll
            for (int j = 0; j < 4; j++) {
                u64 w1p = pk2(w1v[j], w1v[j]);
                u64 b1p = pk2(b1v[j], b1v[j]);
                h1[k][pp][j] = relu2(fma2(w1p, xp[k][pp], b1p));
            }

    float m1[4], inv1[4];
#pragma unroll
    for (int j = 0; j < 4; j++) {
        u64 s = add2(add2(h1[0][0][j], h1[0][1][j]), add2(h1[1][0][j], h1[1][1][j]));
        u64 q = mul2(h1[0][0][j], h1[0][0][j]);
        q = fma2(h1[0][1][j], h1[0][1][j], q);
        q = fma2(h1[1][0][j], h1[1][0][j], q);
        q = fma2(h1[1][1][j], h1[1][1][j], q);
        float sx, sy, qx, qy;
        upk2(s, sx, sy); upk2(q, qx, qy);
        float2 ss = warp_sum2(make_float2(sx + sy, qx + qy));
        float m = ss.x * (1.0f / BATCH);
        float var = fmaxf(ss.y * (1.0f / BATCH) - m * m, 0.0f);
        m1[j] = m;
        inv1[j] = rsqrtf(var + EPS);
    }

    float w2f[16], b2f[4];
    {
        float4 w2q0 = *reinterpret_cast<const float4*>(w2 + 16 * g);
        float4 w2q1 = *reinterpret_cast<const float4*>(w2 + 16 * g + 4);
        float4 w2q2 = *reinterpret_cast<const float4*>(w2 + 16 * g + 8);
        float4 w2q3 = *reinterpret_cast<const float4*>(w2 + 16 * g + 12);
        float w2v[16] = {w2q0.x, w2q0.y, w2q0.z, w2q0.w,
                         w2q1.x, w2q1.y, w2q1.z, w2q1.w,
                         w2q2.x, w2q2.y, w2q2.z, w2q2.w,
                         w2q3.x, w2q3.y, w2q3.z, w2q3.w};
#pragma unroll
        for (int i = 0; i < 4; i++) {
            float bb = b2v[i];
#pragma unroll
            for (int j = 0; j < 4; j++) {
                float wf = w2v[4 * i + j] * inv1[j];
                w2f[4 * i + j] = wf;
                bb -= wf * m1[j];
            }
            b2f[i] = bb;
        }
    }

    u64 h2[2][2][4];
#pragma unroll
    for (int k = 0; k < 2; k++)
#pragma unroll
        for (int pp = 0; pp < 2; pp++)
#pragma unroll
            for (int i = 0; i < 4; i++) {
                u64 acc = pk2(b2f[i], b2f[i]);
#pragma unroll
                for (int j = 0; j < 4; j++) {
                    u64 wp = pk2(w2f[4 * i + j], w2f[4 * i + j]);
                    acc = fma2(wp, h1[k][pp][j], acc);
                }
                h2[k][pp][i] = relu2(acc);
            }

#pragma unroll
    for (int i = 0; i < 4; i++) {
        u64 s = add2(add2(h2[0][0][i], h2[0][1][i]), add2(h2[1][0][i], h2[1][1][i]));
        u64 q = mul2(h2[0][0][i], h2[0][0][i]);
        q = fma2(h2[0][1][i], h2[0][1][i], q);
        q = fma2(h2[1][0][i], h2[1][0][i], q);
        q = fma2(h2[1][1][i], h2[1][1][i], q);
        float sx, sy, qx, qy;
        upk2(s, sx, sy); upk2(q, qx, qy);
        float2 ss = warp_sum2(make_float2(sx + sy, qx + qy));
        float m = ss.x * (1.0f / BATCH);
        float var = fmaxf(ss.y * (1.0f / BATCH) - m * m, 0.0f);
        float inv = rsqrtf(var + EPS);

        u64 inv2 = pk2(inv, inv);
        u64 sh2  = pk2(-m * inv, -m * inv);
        __half2* dst = reinterpret_cast<__half2*>(&g_hT[(4 * g + i) * BATCH]);
#pragma unroll
        for (int k = 0; k < 2; k++) {
            u64 p0 = fma2(h2[k][0][i], inv2, sh2);
            u64 p1 = fma2(h2[k][1][i], inv2, sh2);
            float a0, a1, a2, a3;
            upk2(p0, a0, a1); upk2(p1, a2, a3);
            H22 hv;
            hv.a = __floats2half2_rn(a0, a1);
            hv.b = __floats2half2_rn(a2, a3);
            *reinterpret_cast<H22*>(&dst[64 * k + 2 * lane]) = hv;
        }
    }

    // PDL: this block's g_hT writes are done — allow the dependent grid.
    cudaTriggerProgrammaticLaunchCompletion();
}

// layer3 (R14 body) + PDL: prologue (w3/cols3/b3) runs concurrently with the
// tail of k_layers12; cudaGridDependencySynchronize() gates the g_hT gather.
struct __align__(8) WC { float w; int boff; };

__device__ __forceinline__ void fma8(float* acc, float w, const uint4& v) {
    float2 f0 = __half22float2(*reinterpret_cast<const __half2*>(&v.x));
    float2 f1 = __half22float2(*reinterpret_cast<const __half2*>(&v.y));
    float2 f2 = __half22float2(*reinterpret_cast<const __half2*>(&v.z));
    float2 f3 = __half22float2(*reinterpret_cast<const __half2*>(&v.w));
    acc[0] = fmaf(w, f0.x, acc[0]);
    acc[1] = fmaf(w, f0.y, acc[1]);
    acc[2] = fmaf(w, f1.x, acc[2]);
    acc[3] = fmaf(w, f1.y, acc[3]);
    acc[4] = fmaf(w, f2.x, acc[4]);
    acc[5] = fmaf(w, f2.y, acc[5]);
    acc[6] = fmaf(w, f3.x, acc[6]);
    acc[7] = fmaf(w, f3.y, acc[7]);
}

__global__ __launch_bounds__(256) void k_layer3(
    const float* __restrict__ w3, const float* __restrict__ b3,
    const int* __restrict__ cols3,
    float* __restrict__ out)   // [BATCH, N_TF]
{
    const int tf = blockIdx.x;
    const int t = threadIdx.x;        // 0..255
    const int warp = t >> 5;
    const int lane = t & 31;

    __shared__ WC swc[EDGES3];
    __shared__ float sacc[8][BATCH];      // 8 KB
    __shared__ float2 sred[8];

    // Prologue: independent of g_hT — overlaps with k_layers12's tail.
    swc[t].w    = w3[tf * EDGES3 + t];
    swc[t].boff = cols3[tf * EDGES3 + t] * (BATCH * 2);   // bytes
    float bias = b3[tf];
    __syncthreads();

    // Wait for all k_layers12 blocks to have triggered (g_hT visible).
    cudaGridDependencySynchronize();

    const char* hbase = reinterpret_cast<const char*>(g_hT) + lane * 16;
    const int ebase = warp * 32;

    float acc[8];
#pragma unroll
    for (int s = 0; s < 8; s++) acc[s] = 0.f;

#pragma unroll
    for (int c = 0; c < 8; c++) {
        WC a0 = swc[ebase + 4 * c + 0];
        WC a1 = swc[ebase + 4 * c + 1];
        WC a2 = swc[ebase + 4 * c + 2];
        WC a3 = swc[ebase + 4 * c + 3];
        uint4 v0 = *reinterpret_cast<const uint4*>(hbase + a0.boff);
        uint4 v1 = *reinterpret_cast<const uint4*>(hbase + a1.boff);
        uint4 v2 = *reinterpret_cast<const uint4*>(hbase + a2.boff);
        uint4 v3 = *reinterpret_cast<const uint4*>(hbase + a3.boff);
        fma8(acc, a0.w, v0);
        fma8(acc, a1.w, v1);
        fma8(acc, a2.w, v2);
        fma8(acc, a3.w, v3);
    }

    // Park partials: warp's acc[s] is batch 8*lane+s
    *reinterpret_cast<float4*>(&sacc[warp][8 * lane])     = make_float4(acc[0], acc[1], acc[2], acc[3]);
    *reinterpret_cast<float4*>(&sacc[warp][8 * lane + 4]) = make_float4(acc[4], acc[5], acc[6], acc[7]);
    __syncthreads();

    // Thread t owns batch b = t: sum over the 8 warps' partials.
    float z = bias;
#pragma unroll
    for (int w = 0; w < 8; w++) z += sacc[w][t];

    // Single-pass BN over the 256 batch values.
    float2 ss = warp_sum2(make_float2(z, z * z));
    if (lane == 0) sred[warp] = ss;
    __syncthreads();
    float S = 0.f, S2 = 0.f;
#pragma unroll
    for (int i = 0; i < 8; i++) { S += sred[i].x; S2 += sred[i].y; }
    float m = S * (1.0f / BATCH);
    float var = fmaxf(S2 * (1.0f / BATCH) - m * m, 0.0f);
    float inv = rsqrtf(var + EPS);

    out[t * N_TF + tf] = (z - m) * inv;
}

extern "C" void kernel_launch(void* const* d_in, const int* in_sizes, int n_in,
                              void* d_out, int out_size)
{
    const float* x  = (const float*)d_in[0];
    const float* w1 = (const float*)d_in[1];
    const float* b1 = (const float*)d_in[2];
    const float* w2 = (const float*)d_in[3];
    const float* b2 = (const float*)d_in[4];
    const float* w3 = (const float*)d_in[5];
    const float* b3 = (const float*)d_in[6];
    const int* cols3 = (const int*)d_in[12];
    float* out = (float*)d_out;

    k_layers12<<<N_GENES / GENES_PER_BLOCK, 256>>>(x, w1, b1, w2, b2);

    // PDL launch: k_layer3 may begin its prologue before k_layers12 fully
    // completes; cudaGridDependencySynchronize() inside gates the gather.
    cudaLaunchConfig_t cfg = {};
    cfg.gridDim  = dim3(N_TF);
    cfg.blockDim = dim3(256);
    cfg.stream   = 0;
    cudaLaunchAttribute attrs[1];
    attrs[0].id = cudaLaunchAttributeProgrammaticStreamSerialization;
    attrs[0].val.programmaticStreamSerializationAllowed = 1;
    cfg.attrs = attrs;
    cfg.numAttrs = 1;
    cudaLaunchKernelEx(&cfg, k_layer3, w3, b3, cols3, out);
}